// round 8
// baseline (speedup 1.0000x reference)
#include <cuda_runtime.h>
#include <cuda_bf16.h>

// SpatialConsistencyLoss — fused kernel with neighbor-flag sync (no grid barrier).
//   original, enhanced: [32,3,512,512] f32
//   p = avg_pool4(mean_c(orig)) - avg_pool4(mean_c(enh))   [32,128,128]
//   loss[i,j] = sum_dirs (p[i,j] - p[nbr])^2, zero-padded  -> [32,1,128,128]
//
// 2048 blocks, one pooled pixel per thread (same streaming structure as the
// 6.4 TB/s standalone pool kernel). Block k owns pooled rows {2k, 2k+1}
// (64 blocks per image; blocks never straddle images). Loss needs only rows
// from blocks k-1 / k+1, so sync is per-row ready flags, not a grid barrier:
//   writer: store rows -> threadfence -> set flag (only if a consumer exists)
//   consumer: spin on flag -> reset it (self-cleaning => deterministic
//             across graph replays; flags return to 0 every launch)
// Chain dependency + sliding resident window => deadlock-free; blocks retire
// as they finish, so no residency/launch_bounds constraint.

#define B 32
#define HP 128
#define WP 128
#define NPOOL (B * HP * WP)
#define HIN 512
#define WIN 512
#define CH_STRIDE (HIN * WIN)          // 262144
#define IMG_STRIDE (3 * CH_STRIDE)     // 786432
#define THREADS 256
#define NBLOCKS (NPOOL / THREADS)      // 2048
#define TOTAL_ROWS (B * HP)            // 4096

__device__ float g_pooled[NPOOL];               // 2 MB scratch
__device__ unsigned int g_flag[TOTAL_ROWS];     // zero-init; protocol restores 0

__device__ __forceinline__ float sq(float x) { return x * x; }

__global__ void scl_flag_kernel(const float* __restrict__ orig,
                                const float* __restrict__ enh,
                                float* __restrict__ out) {
    const int k   = blockIdx.x;
    const int gr0 = k << 1;                  // first global pooled row of block
    const int row = threadIdx.x >> 7;        // 0 or 1
    const int col = threadIdx.x & (WP - 1);
    const int gr  = gr0 + row;               // global row = b*128 + i
    const int b   = gr >> 7;
    const int i   = gr & (HP - 1);

    __shared__ float sp[2][WP];

    // ---- Phase 1: one pooled pixel per thread (24 warp-contiguous LDG.128) ----
    const int base0 = b * IMG_STRIDE + (i * 4) * WIN + col * 4;
    float s = 0.0f;
#pragma unroll
    for (int c = 0; c < 3; ++c) {
        int base = base0 + c * CH_STRIDE;
#pragma unroll
        for (int r = 0; r < 4; ++r) {
            float4 ov = *reinterpret_cast<const float4*>(orig + base + r * WIN);
            float4 ev = *reinterpret_cast<const float4*>(enh  + base + r * WIN);
            s += (ov.x - ev.x) + (ov.y - ev.y) + (ov.z - ev.z) + (ov.w - ev.w);
        }
    }
    const float v = s * (1.0f / 48.0f);      // /3 channels, /16 pool

    sp[row][col] = v;
    g_pooled[(gr << 7) + col] = v;
    __threadfence();                          // order data before flag (release)
    __syncthreads();

    // Consumer-existence == waiter-existence conditions (exactly matched):
    //   row gr0   is consumed by block k-1 iff i(gr0)   != 0
    //   row gr0+1 is consumed by block k+1 iff i(gr0+1) != 127
    const bool need_up = (gr0 & (HP - 1)) != 0;            // we wait on gr0-1
    const bool need_dn = ((gr0 + 1) & (HP - 1)) != HP - 1; // we wait on gr0+2

    // Publish first (both flags), then spin — no pairwise stall.
    if (threadIdx.x == 0 && need_up)   // flag[gr0] consumed iff i(gr0)!=0 == need_up
        atomicExch(&g_flag[gr0], 1u);
    if (threadIdx.x == 32 && need_dn)  // flag[gr0+1] consumed iff i(gr0+1)!=127 == need_dn
        atomicExch(&g_flag[gr0 + 1], 1u);

    if (threadIdx.x == 0 && need_up) {
        while (atomicAdd(&g_flag[gr0 - 1], 0u) == 0u) { }
        atomicExch(&g_flag[gr0 - 1], 0u);    // self-clean for next replay
        __threadfence();                      // acquire neighbor's data
    }
    if (threadIdx.x == 32 && need_dn) {
        while (atomicAdd(&g_flag[gr0 + 2], 0u) == 0u) { }
        atomicExch(&g_flag[gr0 + 2], 0u);
        __threadfence();
    }
    __syncthreads();

    // ---- Phase 2: loss for this thread's pixel ----
    float up, dn;
    if (row == 1)       up = sp[0][col];
    else if (need_up)   up = g_pooled[((gr0 - 1) << 7) + col];
    else                up = 0.0f;

    if (row == 0)       dn = sp[1][col];
    else if (need_dn)   dn = g_pooled[((gr0 + 2) << 7) + col];
    else                dn = 0.0f;

    float left  = (col > 0)      ? sp[row][col - 1] : 0.0f;
    float right = (col < WP - 1) ? sp[row][col + 1] : 0.0f;

    out[(gr << 7) + col] =
        sq(v - left) + sq(v - right) + sq(v - up) + sq(v - dn);
}

extern "C" void kernel_launch(void* const* d_in, const int* in_sizes, int n_in,
                              void* d_out, int out_size) {
    const float* orig = (const float*)d_in[0];
    const float* enh  = (const float*)d_in[1];
    float* out = (float*)d_out;

    scl_flag_kernel<<<NBLOCKS, THREADS>>>(orig, enh, out);
}

// round 9
// speedup vs baseline: 1.0791x; 1.0791x over previous
#include <cuda_runtime.h>
#include <cuda_bf16.h>

// SpatialConsistencyLoss — two kernels, loss overlapped via PDL.
//   original, enhanced: [32,3,512,512] f32
//   p = avg_pool4(mean_c(orig)) - avg_pool4(mean_c(enh))   [32,128,128]
//   loss[i,j] = sum_dirs (p[i,j] - p[nbr])^2, zero-padded  -> [32,1,128,128]
//
// Pool kernel is the proven 6.4 TB/s streaming body (one pooled pixel per
// thread, 24 warp-contiguous LDG.128). Loss kernel is launched with
// programmatic stream serialization: its blocks dispatch + run their
// preamble during the pool tail, and cudaGridDependencySynchronize() gates
// the g_pooled reads. This hides the launch/dispatch/ramp cost that made
// the standalone loss pass 4.9us, without touching the streaming phase
// (fused variants all degraded the stream 10-20%).

#define B 32
#define HP 128
#define WP 128
#define NPOOL (B * HP * WP)   // 524288
#define HIN 512
#define WIN 512
#define CH_STRIDE (HIN * WIN)          // 262144
#define IMG_STRIDE (3 * CH_STRIDE)     // 786432

__device__ float g_pooled[NPOOL];   // 2 MB scratch

__device__ __forceinline__ float sq(float x) { return x * x; }

__global__ void pool_diff_kernel(const float* __restrict__ orig,
                                 const float* __restrict__ enh) {
    int idx = blockIdx.x * blockDim.x + threadIdx.x;

    int j = idx & (WP - 1);
    int i = (idx >> 7) & (HP - 1);
    int b = idx >> 14;

    int base0 = b * IMG_STRIDE + (i * 4) * WIN + (j * 4);

    float s = 0.0f;
#pragma unroll
    for (int c = 0; c < 3; ++c) {
        int base = base0 + c * CH_STRIDE;
#pragma unroll
        for (int r = 0; r < 4; ++r) {
            float4 ov = *reinterpret_cast<const float4*>(orig + base + r * WIN);
            float4 ev = *reinterpret_cast<const float4*>(enh  + base + r * WIN);
            s += (ov.x - ev.x) + (ov.y - ev.y) + (ov.z - ev.z) + (ov.w - ev.w);
        }
    }
    g_pooled[idx] = s * (1.0f / 48.0f);   // /3 channels, /16 pool

    // Let the PDL-launched loss kernel start dispatching while remaining
    // pool blocks drain. (Fires per-block; dependency completes when all
    // blocks have triggered.)
    cudaTriggerProgrammaticLaunchCompletion();
}

// One thread = 4 adjacent output pixels (float4 along j).
__global__ void loss_kernel_v4(float* __restrict__ out) {
    // Preamble runs BEFORE the dependency sync — overlapped with pool tail.
    int t = blockIdx.x * blockDim.x + threadIdx.x;   // 0 .. NPOOL/4 - 1

    int j4  = (t & 31) << 2;      // 0,4,...,124 : first j of the quad
    int row = t >> 5;             // b*128 + i
    int i   = row & (HP - 1);
    int base = (row << 7) + j4;

    const float4* p4 = reinterpret_cast<const float4*>(g_pooled);
    int ci = base >> 2;
    int ui = (base - WP) >> 2;
    int di = (base + WP) >> 2;
    bool has_up = (i > 0);
    bool has_dn = (i < HP - 1);
    bool has_l  = (j4 > 0);
    bool has_r  = (j4 < WP - 4);

    // Wait for all pool blocks to finish writing g_pooled.
    cudaGridDependencySynchronize();

    float4 c  = p4[ci];
    float4 up = has_up ? p4[ui] : make_float4(0.f, 0.f, 0.f, 0.f);
    float4 dn = has_dn ? p4[di] : make_float4(0.f, 0.f, 0.f, 0.f);
    float left  = has_l ? g_pooled[base - 1] : 0.f;
    float right = has_r ? g_pooled[base + 4] : 0.f;

    float4 o;
    o.x = sq(c.x - left) + sq(c.x - c.y)   + sq(c.x - up.x) + sq(c.x - dn.x);
    o.y = sq(c.y - c.x)  + sq(c.y - c.z)   + sq(c.y - up.y) + sq(c.y - dn.y);
    o.z = sq(c.z - c.y)  + sq(c.z - c.w)   + sq(c.z - up.z) + sq(c.z - dn.z);
    o.w = sq(c.w - c.z)  + sq(c.w - right) + sq(c.w - up.w) + sq(c.w - dn.w);

    reinterpret_cast<float4*>(out)[base >> 2] = o;
}

extern "C" void kernel_launch(void* const* d_in, const int* in_sizes, int n_in,
                              void* d_out, int out_size) {
    const float* orig = (const float*)d_in[0];
    const float* enh  = (const float*)d_in[1];
    float* out = (float*)d_out;

    const int threads = 256;

    pool_diff_kernel<<<NPOOL / threads, threads>>>(orig, enh);

    // Loss kernel with programmatic dependent launch: overlap dispatch/ramp
    // with the pool kernel's tail.
    cudaLaunchConfig_t cfg = {};
    cfg.gridDim  = dim3(NPOOL / 4 / threads);   // 512
    cfg.blockDim = dim3(threads);
    cudaLaunchAttribute attr[1];
    attr[0].id = cudaLaunchAttributeProgrammaticStreamSerialization;
    attr[0].val.programmaticStreamSerializationAllowed = 1;
    cfg.attrs = attr;
    cfg.numAttrs = 1;
    cudaLaunchKernelEx(&cfg, loss_kernel_v4, out);
}